// round 17
// baseline (speedup 1.0000x reference)
#include <cuda_runtime.h>

// PartialMatchingLoss via counting-sorted uniform grid, warp-per-query.
// B=8, M=4096 queries (partial), N=8192 points (completed), D=3.
//
// Points are counting-sorted by cell (row-major x-fastest) into a dense
// per-batch float4 array (128 KB/batch, L2-resident). A query row's cells
// [qx-k, qx+k] form ONE contiguous range [start[left], start[right+1]) --
// the warp broadcasts each row range and stripes lanes over contiguous
// points => coalesced loads (few L1 wavefronts) instead of per-lane gathers.
//
// Search: cube-1 (9 rows) -> cube-2 (25 rows) -> cube-4 (81 rows) -> full
// scan. After finishing cube k, any unvisited point differs by >= k*h in
// some axis (clamped queries get an even larger gap), so stop when
// best2 <= (k*h)^2. Exact NN, no caps/overflow.
//
// Determinism: within-cell order depends on atomic timing, but min over the
// same point multiset is order-invariant; all sums are fixed-order. kS
// re-zeroes the count array each launch (static init covers launch 1), so
// every graph replay starts from identical state.

#define B_ 8
#define M_ 4096
#define N_ 8192
#define TOTAL_P (B_ * M_)            // 32768

#define GDIM 32
#define GLO  (-4.0f)
#define GH   0.25f
#define INVH 4.0f
#define CELLS_PER_B (GDIM * GDIM * GDIM)   // 32768
#define NCELLS (B_ * CELLS_PER_B)          // 262144
#define STARTN (CELLS_PER_B + 1)           // +1 sentinel per batch

#define KC_THREADS 256
#define QPC (KC_THREADS / 32)              // 8 queries per CTA
#define KC_CTAS (TOTAL_P / QPC)            // 4096

__device__ unsigned int g_cellcnt[NCELLS];       // 1 MB; re-zeroed by kS
__device__ unsigned int g_start[B_][STARTN];     // exclusive prefix + sentinel
__device__ unsigned int g_cursor[NCELLS];        // scatter cursors (= start copy)
__device__ float4       g_sorted[B_ * N_];       // 1 MB dense sorted points
__device__ float        g_blocksum[KC_CTAS];
__device__ unsigned int g_tick;                  // zero-init; reset each launch

__device__ __forceinline__ int cell_of(float v) {
    int c = (int)floorf((v - GLO) * INVH);
    return min(max(c, 0), GDIM - 1);
}

// ---------------- kB1: count points per cell ----------------
__global__ void kB1_count(const float* __restrict__ completed) {
    int i = blockIdx.x * blockDim.x + threadIdx.x;   // 65536 = B_*N_
    int b = i >> 13;
    const float* c = completed + (size_t)i * 3;
    int cid = b * CELLS_PER_B +
              (cell_of(c[2]) * GDIM + cell_of(c[1])) * GDIM + cell_of(c[0]);
    atomicAdd(&g_cellcnt[cid], 1u);
}

// ---------------- kS: per-batch exclusive scan; also zero counts ------------
// 8 CTAs (one per batch) x 1024 threads; each thread owns 32 cells.
__global__ void __launch_bounds__(1024)
kS_scan() {
    __shared__ unsigned warpsum[32];
    const int b = blockIdx.x;
    const int tid = threadIdx.x;
    const int lane = tid & 31, wid = tid >> 5;
    const unsigned base = b * CELLS_PER_B + tid * 32;

    unsigned v[32];
    uint4* cp = (uint4*)(g_cellcnt + base);
#pragma unroll
    for (int i = 0; i < 8; i++) {
        uint4 w = cp[i];
        v[4 * i] = w.x; v[4 * i + 1] = w.y; v[4 * i + 2] = w.z; v[4 * i + 3] = w.w;
    }
    unsigned tsum = 0;
#pragma unroll
    for (int i = 0; i < 32; i++) tsum += v[i];

    // Block exclusive scan of per-thread sums.
    unsigned sc = tsum;
#pragma unroll
    for (int o = 1; o < 32; o <<= 1) {
        unsigned n = __shfl_up_sync(0xFFFFFFFFu, sc, o);
        if (lane >= o) sc += n;
    }
    if (lane == 31) warpsum[wid] = sc;
    __syncthreads();
    if (wid == 0) {
        unsigned ws = warpsum[lane];
#pragma unroll
        for (int o = 1; o < 32; o <<= 1) {
            unsigned n = __shfl_up_sync(0xFFFFFFFFu, ws, o);
            if (lane >= o) ws += n;
        }
        warpsum[lane] = ws;
    }
    __syncthreads();
    unsigned run = sc - tsum + (wid ? warpsum[wid - 1] : 0u);

    // Emit starts + cursors; zero counts for the next launch.
#pragma unroll
    for (int i = 0; i < 32; i++) {
        g_start[b][tid * 32 + i] = run;
        g_cursor[base + i] = run;
        run += v[i];
    }
    uint4 z = make_uint4(0u, 0u, 0u, 0u);
#pragma unroll
    for (int i = 0; i < 8; i++) cp[i] = z;
    if (tid == 0) g_start[b][CELLS_PER_B] = N_;   // sentinel
}

// ---------------- kB3: scatter points into dense sorted array ---------------
__global__ void kB3_scatter(const float* __restrict__ completed) {
    int i = blockIdx.x * blockDim.x + threadIdx.x;   // 65536
    int b = i >> 13;
    const float* c = completed + (size_t)i * 3;
    float x = c[0], y = c[1], z = c[2];
    int cid = b * CELLS_PER_B +
              (cell_of(z) * GDIM + cell_of(y)) * GDIM + cell_of(x);
    unsigned slot = atomicAdd(&g_cursor[cid], 1u);   // within-batch offset
    g_sorted[(size_t)b * N_ + slot] = make_float4(x, y, z, 0.0f);
}

// ---------------- kC: warp-per-query search + fused reduction ---------------
__device__ __forceinline__ float warp_min(float v) {
#pragma unroll
    for (int off = 16; off > 0; off >>= 1)
        v = fminf(v, __shfl_xor_sync(0xFFFFFFFFu, v, off));
    return v;
}

// Visit full cube of Chebyshev radius K around (qx,qy,qz): rows broadcast,
// lanes stripe contiguous points. Uniform control flow across the warp.
template <int K>
__device__ __forceinline__ void visit_cube(int b, int qx, int qy, int qz,
                                           float px, float py, float pz,
                                           int lane, float& best2) {
    const int side = 2 * K + 1;
    const int R = side * side;                 // rows (dy,dz)
    const int xl = max(qx - K, 0), xr = min(qx + K, GDIM - 1);
    const float4* sp = g_sorted + (size_t)b * N_;
    for (int rbase = 0; rbase < R; rbase += 32) {
        int idx = rbase + lane;
        unsigned s = 0u, e = 0u;
        if (idx < R) {
            int dy = idx % side - K;
            int dz = idx / side - K;
            int ry = qy + dy, rz = qz + dz;
            if ((unsigned)ry < GDIM && (unsigned)rz < GDIM) {
                int rb = (rz * GDIM + ry) * GDIM;
                s = g_start[b][rb + xl];
                e = g_start[b][rb + xr + 1];
            }
        }
        int cnt = min(R - rbase, 32);
        for (int j = 0; j < cnt; j++) {
            unsigned sj = __shfl_sync(0xFFFFFFFFu, s, j);
            unsigned ej = __shfl_sync(0xFFFFFFFFu, e, j);
            for (unsigned p = sj + lane; p < ej; p += 32) {
                float4 q = sp[p];
                float dx = px - q.x, dy2 = py - q.y, dz2 = pz - q.z;
                best2 = fminf(best2, fmaf(dx, dx, fmaf(dy2, dy2, dz2 * dz2)));
            }
        }
    }
}

__global__ void __launch_bounds__(KC_THREADS)
kC_query(const float* __restrict__ partial, float* __restrict__ out) {
    __shared__ float swarp[QPC];
    __shared__ int is_last;
    const int tid  = threadIdx.x;
    const int wid  = tid >> 5;
    const int lane = tid & 31;
    const int pid  = blockIdx.x * QPC + wid;   // query id = b*M + m
    const int b    = pid >> 12;

    const float* pp = partial + (size_t)pid * 3;   // broadcast across lanes
    const float px = pp[0], py = pp[1], pz = pp[2];
    const int qx = cell_of(px), qy = cell_of(py), qz = cell_of(pz);

    float best2 = 3.4e38f;

    visit_cube<1>(b, qx, qy, qz, px, py, pz, lane, best2);
    float wbest = warp_min(best2);

    if (wbest > GH * GH) {
        visit_cube<2>(b, qx, qy, qz, px, py, pz, lane, best2);
        wbest = warp_min(best2);

        if (wbest > 4.0f * GH * GH) {
            visit_cube<4>(b, qx, qy, qz, px, py, pz, lane, best2);
            wbest = warp_min(best2);

            if (wbest > 16.0f * GH * GH) {
                // Exact warp-striped coalesced scan (vanishingly rare).
                const float4* sp = g_sorted + (size_t)b * N_;
                for (int i0 = lane; i0 < N_; i0 += 32) {
                    float4 q = sp[i0];
                    float dx = px - q.x, dy = py - q.y, dz = pz - q.z;
                    best2 = fminf(best2, fmaf(dx, dx, fmaf(dy, dy, dz * dz)));
                }
                wbest = warp_min(best2);
            }
        }
    }

    // Per-warp distance -> fixed-order CTA sum -> ticket-last final sum.
    if (lane == 0) swarp[wid] = sqrtf(wbest);
    __syncthreads();
    if (tid == 0) {
        float s = 0.0f;
#pragma unroll
        for (int i = 0; i < QPC; i++) s += swarp[i];      // fixed order
        g_blocksum[blockIdx.x] = s;
        __threadfence();
        unsigned int ticket = atomicAdd(&g_tick, 1u);
        is_last = (ticket == KC_CTAS - 1);
    }
    __syncthreads();

    if (is_last) {
        __shared__ float ssum[KC_THREADS];
        // All g_blocksum writes are visible (each CTA fenced before its ticket).
        float s = 0.0f;
#pragma unroll
        for (int i = 0; i < KC_CTAS / KC_THREADS; i++)    // 16 slots, fixed order
            s += g_blocksum[tid * (KC_CTAS / KC_THREADS) + i];
        ssum[tid] = s;
        __syncthreads();
#pragma unroll
        for (int off = KC_THREADS / 2; off > 0; off >>= 1) {
            if (tid < off) ssum[tid] += ssum[tid + off];
            __syncthreads();
        }
        if (tid == 0) {
            out[0] = ssum[0] * (1.0f / (float)TOTAL_P);
            g_tick = 0u;   // restore for the next graph replay
        }
    }
}

extern "C" void kernel_launch(void* const* d_in, const int* in_sizes, int n_in,
                              void* d_out, int out_size) {
    const float* completed = (const float*)d_in[0];  // (8, 8192, 3)
    const float* partial   = (const float*)d_in[1];  // (8, 4096, 3)
    if (n_in >= 2 && in_sizes[0] == B_ * M_ * 3 && in_sizes[1] == B_ * N_ * 3) {
        completed = (const float*)d_in[1];
        partial   = (const float*)d_in[0];
    }

    kB1_count<<<256, 256>>>(completed);
    kS_scan<<<B_, 1024>>>();
    kB3_scatter<<<256, 256>>>(completed);
    kC_query<<<KC_CTAS, KC_THREADS>>>(partial, (float*)d_out);
}